// round 7
// baseline (speedup 1.0000x reference)
#include <cuda_runtime.h>
#include <cstdint>

#define NB 4
#define NXg 432
#define NYg 496
#define Hc 248
#define Wc 216
#define HW (Hc*Wc)
#define C1 8
#define C2 16
#define COUT 400
#define CSP 384
#define KS 15
#define RAD 7
#define NBN (NB*HW)

// scratch (device globals; no allocation allowed)
__device__ float g_hist[NB*NYg*NXg];
__device__ float g_tmp [NB*NYg*NXg];
__device__ float g_dm  [NB*HW];
__device__ float g_c1  [NB*C1*HW];
__device__ float g_c2  [NB*C2*HW];
__device__ float g_gauss[KS];
__device__ int   g_max[NB];              // float bits, values >= 0
__device__ float g_stats1[2*C1];         // sum, sumsq
__device__ float g_stats2[2*C2];

// ---------------- concat copy, 256-bit granules, pipelined through the chain ----
// Units: one granule = 8 floats = 32 bytes (Blackwell v8.b32 ld/st).
// dst8[i + (i/PER_B8)*DSKIP8] = src8[i], i in [0, COPY_N8).
#define COPY_N8  (NB*CSP*HW/8)           // 10,285,056 granules
#define PER_B8   (CSP*HW/8)              // 2,571,264
#define DSKIP8   ((COUT-CSP)*HW/8)       // 107,136

// shares in granules (sum == COPY_N8); capacity D*threads >= share verified.
#define S_INIT  1700000
#define S_HIST  1000000
#define S_BLX   1200000
#define S_BLY   1200000
#define S_DOWN  700000
#define S_CV1   1800000
#define S_OUT   (COPY_N8 - S_INIT - S_HIST - S_BLX - S_BLY - S_DOWN - S_CV1)
#define O_INIT  0
#define O_HIST  (O_INIT + S_INIT)
#define O_BLX   (O_HIST + S_HIST)
#define O_BLY   (O_BLX + S_BLX)
#define O_DOWN  (O_BLY + S_BLY)
#define O_CV1   (O_DOWN + S_DOWN)
#define O_OUT   (O_CV1 + S_CV1)

template<int D>
struct CopyCtx { uint4 a[D], b[D]; int idx[D]; };

template<int D>
__device__ __forceinline__ void copy_pro(const char* __restrict__ src,
                                         int start, int count, CopyCtx<D>& c) {
    int tid = ((blockIdx.y*gridDim.x + blockIdx.x)*blockDim.x) + threadIdx.x;
    int nth = gridDim.x*gridDim.y*blockDim.x;
    int end = start + count;
    #pragma unroll
    for (int k = 0; k < D; k++) {
        int i = start + tid + k*nth;
        c.idx[k] = (i < end) ? i : -1;
    }
    #pragma unroll
    for (int k = 0; k < D; k++)
        if (c.idx[k] >= 0) {
            const char* p = src + (size_t)c.idx[k]*32;
            asm volatile("ld.global.cs.v8.b32 {%0,%1,%2,%3,%4,%5,%6,%7}, [%8];"
                : "=r"(c.a[k].x), "=r"(c.a[k].y), "=r"(c.a[k].z), "=r"(c.a[k].w),
                  "=r"(c.b[k].x), "=r"(c.b[k].y), "=r"(c.b[k].z), "=r"(c.b[k].w)
                : "l"(p));
        }
}

template<int D>
__device__ __forceinline__ void copy_epi(char* __restrict__ dst, const CopyCtx<D>& c) {
    #pragma unroll
    for (int k = 0; k < D; k++)
        if (c.idx[k] >= 0) {
            int b = c.idx[k] / PER_B8;
            char* p = dst + (size_t)(c.idx[k] + b*DSKIP8)*32;
            asm volatile("st.global.cs.v8.b32 [%0], {%1,%2,%3,%4,%5,%6,%7,%8};"
                :: "l"(p),
                   "r"(c.a[k].x), "r"(c.a[k].y), "r"(c.a[k].z), "r"(c.a[k].w),
                   "r"(c.b[k].x), "r"(c.b[k].y), "r"(c.b[k].z), "r"(c.b[k].w)
                : "memory");
        }
}

__global__ void k_init(const char* __restrict__ cs, char* __restrict__ cd) {
    CopyCtx<4> cc; copy_pro<4>(cs, O_INIT, S_INIT, cc);
    int i = blockIdx.x*blockDim.x + threadIdx.x;
    if (i < NB*NYg*NXg) g_hist[i] = 0.f;
    if (i < KS) {
        const float sig = 6.25f;
        float s = 0.f;
        for (int k = 0; k < KS; k++) {
            float c = (float)(k - RAD);
            s += expf(-c*c/(2.f*sig*sig));
        }
        float c = (float)(i - RAD);
        g_gauss[i] = expf(-c*c/(2.f*sig*sig)) / s;
    }
    if (i < NB)   g_max[i] = 0;
    if (i < 2*C1) g_stats1[i] = 0.f;
    if (i < 2*C2) g_stats2[i] = 0.f;
    copy_epi<4>(cd, cc);
}

__global__ void k_hist(const float* __restrict__ pts, int n,
                       const char* __restrict__ cs, char* __restrict__ cd) {
    CopyCtx<4> cc; copy_pro<4>(cs, O_HIST, S_HIST, cc);
    int i = blockIdx.x*blockDim.x + threadIdx.x;
    if (i < n) {
        const float* p = pts + (size_t)i*5;
        int b = (int)p[0];
        int x = (int)__fdiv_rn(p[1] - 0.0f,  0.16f);
        int y = (int)__fdiv_rn(p[2] + 39.68f, 0.16f);
        x = min(max(x, 0), NXg-1);
        y = min(max(y, 0), NYg-1);
        atomicAdd(&g_hist[(b*NYg + y)*NXg + x], 1.0f);
    }
    copy_epi<4>(cd, cc);
}

__global__ void k_blur_x(const char* __restrict__ cs, char* __restrict__ cd) {
    CopyCtx<2> cc; copy_pro<2>(cs, O_BLX, S_BLX, cc);
    int i = blockIdx.x*blockDim.x + threadIdx.x;
    if (i < NB*NYg*NXg) {
        int x = i % NXg;
        int row = i / NXg;  // b*NYg + y
        float acc = 0.f;
        #pragma unroll
        for (int k = 0; k < KS; k++) {
            int xx = x + k - RAD;
            if (xx >= 0 && xx < NXg)
                acc += g_gauss[k] * g_hist[row*NXg + xx];
        }
        g_tmp[i] = acc;
    }
    copy_epi<2>(cd, cc);
}

// blur in y + fused per-batch max (NYg*NXg divisible by 256 -> block never straddles batch)
__global__ void k_blur_y(const char* __restrict__ cs, char* __restrict__ cd) {
    CopyCtx<2> cc; copy_pro<2>(cs, O_BLY, S_BLY, cc);
    int i = blockIdx.x*blockDim.x + threadIdx.x;
    int x = i % NXg;
    int y = (i / NXg) % NYg;
    int b = i / (NXg*NYg);
    float acc = 0.f;
    #pragma unroll
    for (int k = 0; k < KS; k++) {
        int yy = y + k - RAD;
        if (yy >= 0 && yy < NYg)
            acc += g_gauss[k] * g_tmp[(b*NYg + yy)*NXg + x];
    }
    g_hist[i] = acc;   // blurred result back into g_hist

    __shared__ float sm[256];
    sm[threadIdx.x] = acc; __syncthreads();
    for (int s = 128; s > 0; s >>= 1) {
        if (threadIdx.x < s) sm[threadIdx.x] = fmaxf(sm[threadIdx.x], sm[threadIdx.x+s]);
        __syncthreads();
    }
    if (threadIdx.x == 0) atomicMax(&g_max[b], __float_as_int(sm[0]));
    copy_epi<2>(cd, cc);
}

// jax.image.resize 'linear' antialias=True, 2x downsample:
// taps at 2i-1..2i+2 with weights [1,3,3,1], edge-clipped + renormalized.
__device__ __forceinline__ void taps4(int i, int n, int* j, float* w) {
    const float base[4] = {1.f, 3.f, 3.f, 1.f};
    float s = 0.f;
    #pragma unroll
    for (int k = 0; k < 4; k++) {
        int jj = 2*i - 1 + k;
        j[k] = jj;
        if (jj >= 0 && jj < n) { w[k] = base[k]; s += base[k]; }
        else w[k] = 0.f;
    }
    #pragma unroll
    for (int k = 0; k < 4; k++) w[k] /= s;
}

__global__ void k_down(const char* __restrict__ cs, char* __restrict__ cd) {
    CopyCtx<4> cc; copy_pro<4>(cs, O_DOWN, S_DOWN, cc);
    int i = blockIdx.x*blockDim.x + threadIdx.x;
    if (i < NB*HW) {
        int x = i % Wc;
        int y = (i / Wc) % Hc;
        int b = i / HW;
        int jy[4], jx[4]; float wy[4], wx[4];
        taps4(y, NYg, jy, wy);
        taps4(x, NXg, jx, wx);
        float acc = 0.f;
        #pragma unroll
        for (int a = 0; a < 4; a++) {
            if (wy[a] != 0.f) {
                float r = 0.f;
                #pragma unroll
                for (int c = 0; c < 4; c++) {
                    if (wx[c] != 0.f)
                        r += wx[c] * g_hist[(b*NYg + jy[a])*NXg + jx[c]];
                }
                acc += wy[a] * r;
            }
        }
        float mx = __int_as_float(g_max[b]);
        g_dm[i] = (mx > 0.f) ? acc / mx : acc;
    }
    copy_epi<4>(cd, cc);
}

__global__ void k_conv1(const float* __restrict__ w1,
                        const char* __restrict__ cs, char* __restrict__ cd) {
    CopyCtx<2> cc; copy_pro<2>(cs, O_CV1, S_CV1, cc);
    int bc = blockIdx.y;                 // b*C1 + c
    int b = bc / C1, c = bc % C1;
    int hw = blockIdx.x*blockDim.x + threadIdx.x;
    float v = 0.f;
    if (hw < HW) {
        int x = hw % Wc, y = hw / Wc;
        const float* wp = w1 + c*9;
        const float* in = g_dm + b*HW;
        #pragma unroll
        for (int dy = 0; dy < 3; dy++) {
            int yy = y + dy - 1;
            if (yy < 0 || yy >= Hc) continue;
            #pragma unroll
            for (int dx = 0; dx < 3; dx++) {
                int xx = x + dx - 1;
                if (xx < 0 || xx >= Wc) continue;
                v = fmaf(__ldg(&wp[dy*3+dx]), in[yy*Wc+xx], v);
            }
        }
        g_c1[bc*HW + hw] = v;
    }
    __shared__ float s1[256], s2[256];
    float vv = (hw < HW) ? v : 0.f;
    s1[threadIdx.x] = vv; s2[threadIdx.x] = vv*vv;
    __syncthreads();
    for (int s = 128; s > 0; s >>= 1) {
        if (threadIdx.x < s) { s1[threadIdx.x] += s1[threadIdx.x+s]; s2[threadIdx.x] += s2[threadIdx.x+s]; }
        __syncthreads();
    }
    if (threadIdx.x == 0) {
        atomicAdd(&g_stats1[c], s1[0]);
        atomicAdd(&g_stats1[C1 + c], s2[0]);
    }
    copy_epi<2>(cd, cc);
}

// conv2 with BN1+ReLU applied inline to raw conv1 output. No copy share:
// this is the longest pure-compute kernel; the bytes ride in the others.
__global__ void k_conv2(const float* __restrict__ w2,
                        const float* __restrict__ gamma1, const float* __restrict__ beta1) {
    int bc = blockIdx.y;                 // b*C2 + co
    int b = bc / C2, co = bc % C2;
    __shared__ float ws[C1*9];
    __shared__ float sc1[C1], sh1[C1];
    if (threadIdx.x < C1*9) ws[threadIdx.x] = w2[co*C1*9 + threadIdx.x];
    if (threadIdx.x < C1) {
        int c = threadIdx.x;
        float mean = g_stats1[c] / (float)NBN;
        float var  = g_stats1[C1+c] / (float)NBN - mean*mean;
        float s    = gamma1[c] * rsqrtf(var + 1e-3f);
        sc1[c] = s; sh1[c] = beta1[c] - mean*s;
    }
    __syncthreads();
    int hw = blockIdx.x*blockDim.x + threadIdx.x;
    float v = 0.f;
    if (hw < HW) {
        int x = hw % Wc, y = hw / Wc;
        #pragma unroll
        for (int ci = 0; ci < C1; ci++) {
            const float* in = g_c1 + (b*C1 + ci)*HW;
            const float* wp = ws + ci*9;
            float a = sc1[ci], s0 = sh1[ci];
            #pragma unroll
            for (int dy = 0; dy < 3; dy++) {
                int yy = y + dy - 1;
                if (yy < 0 || yy >= Hc) continue;
                #pragma unroll
                for (int dx = 0; dx < 3; dx++) {
                    int xx = x + dx - 1;
                    if (xx < 0 || xx >= Wc) continue;
                    float t = fmaxf(fmaf(in[yy*Wc+xx], a, s0), 0.f);
                    v = fmaf(wp[dy*3+dx], t, v);
                }
            }
        }
        g_c2[bc*HW + hw] = v;
    }
    __shared__ float s1[256], s2[256];
    float vv = (hw < HW) ? v : 0.f;
    s1[threadIdx.x] = vv; s2[threadIdx.x] = vv*vv;
    __syncthreads();
    for (int s = 128; s > 0; s >>= 1) {
        if (threadIdx.x < s) { s1[threadIdx.x] += s1[threadIdx.x+s]; s2[threadIdx.x] += s2[threadIdx.x+s]; }
        __syncthreads();
    }
    if (threadIdx.x == 0) {
        atomicAdd(&g_stats2[co], s1[0]);
        atomicAdd(&g_stats2[C2 + co], s2[0]);
    }
}

// BN2 affine computed per-block, relu, scatter into concat slot.
__global__ void k_out(float* __restrict__ out,
                      const float* __restrict__ gamma, const float* __restrict__ beta,
                      const char* __restrict__ cs, char* __restrict__ cd) {
    CopyCtx<4> cc; copy_pro<4>(cs, O_OUT, S_OUT, cc);
    __shared__ float sc[C2], sh[C2];
    if (threadIdx.x < C2) {
        int c = threadIdx.x;
        float mean = g_stats2[c] / (float)NBN;
        float var  = g_stats2[C2+c] / (float)NBN - mean*mean;
        float s    = gamma[c] * rsqrtf(var + 1e-3f);
        sc[c] = s; sh[c] = beta[c] - mean*s;
    }
    __syncthreads();
    int i = blockIdx.x*blockDim.x + threadIdx.x;
    if (i < NB*C2*HW) {
        int hw = i % HW;
        int c  = (i / HW) % C2;
        int b  = i / (C2*HW);
        float v = fmaxf(fmaf(g_c2[i], sc[c], sh[c]), 0.f);
        out[((size_t)b*COUT + CSP + c)*HW + hw] = v;
    }
    copy_epi<4>(cd, cc);
}

extern "C" void kernel_launch(void* const* d_in, const int* in_sizes, int n_in,
                              void* d_out, int out_size) {
    const float* spatial = (const float*)d_in[0];
    const float* points  = (const float*)d_in[1];
    const float* w1      = (const float*)d_in[2];
    const float* gamma1  = (const float*)d_in[3];
    const float* beta1   = (const float*)d_in[4];
    const float* w2      = (const float*)d_in[5];
    const float* gamma2  = (const float*)d_in[6];
    const float* beta2   = (const float*)d_in[7];
    float* out = (float*)d_out;
    int npts = in_sizes[1] / 5;

    const char* cs = (const char*)spatial;
    char* cd = (char*)out;

    int total = NB*NYg*NXg;
    k_init  <<<(total + 255)/256, 256>>>(cs, cd);
    k_hist  <<<(npts + 255)/256, 256>>>(points, npts, cs, cd);
    k_blur_x<<<(total + 255)/256, 256>>>(cs, cd);
    k_blur_y<<<total/256, 256>>>(cs, cd);
    k_down  <<<(NB*HW + 255)/256, 256>>>(cs, cd);
    { dim3 g((HW + 255)/256, NB*C1); k_conv1<<<g, 256>>>(w1, cs, cd); }
    { dim3 g((HW + 255)/256, NB*C2); k_conv2<<<g, 256>>>(w2, gamma1, beta1); }
    k_out   <<<(NB*C2*HW + 255)/256, 256>>>(out, gamma2, beta2, cs, cd);
}